// round 6
// baseline (speedup 1.0000x reference)
#include <cuda_runtime.h>
#include <cstdint>

// Problem: DetectionFocalLoss. Inputs (metadata order):
//   d_in[0] classifications float32 (B,N,C)
//   d_in[1] regressions     float32 (B,N,4)
//   d_in[2] anchors         float32 (1,N,4)  [cx,cy,w,h]
//   d_in[3] annotations     float32 (B,M,5)  [x1,y1,x2,y2,cls]
// Output: float32[2] = (mean cls_loss, reg entry ratio)

#define TPB 256
#define NBMAX 4096
#define BMAX 16
#define MMAX 128

__device__ float g_pcl[BMAX * NBMAX];
__device__ float g_psl[BMAX * NBMAX];
__device__ float g_pct[BMAX * NBMAX];

__device__ __forceinline__ float clip_cls(float x) {
    const float CEPS = 1e-4f;
    const float CMAX = 1.0f - 1e-4f;
    return fminf(fmaxf(x, CEPS), CMAX);
}

// focal term for label==0:  (1-ALPHA) * cls^2 * (-log(1-cls))
__device__ __forceinline__ float f_neg(float x) {
    float xc = clip_cls(x);
    return 0.75f * xc * xc * (-__logf(1.0f - xc));
}

__global__ __launch_bounds__(TPB)
void assign_kernel(const float* __restrict__ cls_,
                   const float* __restrict__ reg_,
                   const float* __restrict__ anc,
                   const float* __restrict__ ann,
                   int N, int C, int M, int NB)
{
    __shared__ float s_ann[MMAX * 5];
    __shared__ float s_area[MMAX];
    __shared__ float r_cl[TPB];
    __shared__ float r_sl[TPB];
    __shared__ int   r_ct[TPB];

    const int b   = blockIdx.y;
    const int tid = threadIdx.x;
    const int n   = blockIdx.x * TPB + tid;

    // stage annotations for this batch
    for (int i = tid; i < M * 5; i += TPB)
        s_ann[i] = ann[(size_t)b * M * 5 + i];
    __syncthreads();
    if (tid < M) {
        float x1 = s_ann[tid * 5 + 0], y1 = s_ann[tid * 5 + 1];
        float x2 = s_ann[tid * 5 + 2], y2 = s_ann[tid * 5 + 3];
        s_area[tid] = (x2 - x1) * (y2 - y1);
    }
    __syncthreads();

    float cl_local = 0.0f;
    float sl_local = 0.0f;
    int   pos_local = 0;

    if (n < N) {
        // anchor in (cx,cy,w,h) -> tp box (x1,y1,x2,y2)
        float4 a = reinterpret_cast<const float4*>(anc)[n];
        float t0 = a.x - a.z * 0.5f;
        float t1 = a.y - a.w * 0.5f;
        float t2 = a.x + a.z * 0.5f;
        float t3 = a.y + a.w * 0.5f;
        float area_a = (t2 - t0) * (t3 - t1);

        // IoU max / argmax over M annotations (first-max like jnp.argmax)
        float best = -1.0f;
        int   bi = 0;
        #pragma unroll 4
        for (int m = 0; m < M; m++) {
            float b0 = s_ann[m * 5 + 0], b1 = s_ann[m * 5 + 1];
            float b2 = s_ann[m * 5 + 2], b3 = s_ann[m * 5 + 3];
            float lx = fmaxf(t0, b0), ly = fmaxf(t1, b1);
            float rx = fminf(t2, b2), ry = fminf(t3, b3);
            float wi = fmaxf(rx - lx, 0.0f);
            float hi = fmaxf(ry - ly, 0.0f);
            float inter = wi * hi;
            float uni = area_a + s_area[m] - inter;
            float iou = inter / fmaxf(uni, 1e-8f);
            if (iou > best) { best = iou; bi = m; }
        }

        bool pos = (best >= 0.5f);
        bool neg = (best <= 0.4f);

        if (pos || neg) {
            const float* cp = cls_ + ((size_t)b * N + n) * C;
            float s = 0.0f;
            if ((C & 3) == 0) {
                const float4* cp4 = reinterpret_cast<const float4*>(cp);
                int C4 = C >> 2;
                #pragma unroll 5
                for (int i = 0; i < C4; i++) {
                    float4 v = cp4[i];
                    s += f_neg(v.x) + f_neg(v.y) + f_neg(v.z) + f_neg(v.w);
                }
            } else {
                for (int c = 0; c < C; c++) s += f_neg(cp[c]);
            }

            if (pos) {
                pos_local = 1;
                int cid = (int)s_ann[bi * 5 + 4];
                // replace label-0 term with label-1 term for target class
                float x = clip_cls(cp[cid]);
                s -= 0.75f * x * x * (-__logf(1.0f - x));
                float om = 1.0f - x;
                s += 0.25f * om * om * (-__logf(x));

                // smooth-L1 regression term
                float4 r = reinterpret_cast<const float4*>(reg_)[(size_t)b * N + n];
                float g0 = s_ann[bi * 5 + 0], g1 = s_ann[bi * 5 + 1];
                float g2 = s_ann[bi * 5 + 2], g3 = s_ann[bi * 5 + 3];
                float dw  = g2 - g0;
                float dh  = g3 - g1;
                float dxc = g0 + g2 * 0.5f;   // replicate reference exactly
                float dyc = g1 + g3 * 0.5f;
                float dx  = (dxc - a.x) / a.z;
                float dy  = (dyc - a.y) / a.w;
                float dwl = __logf(dw / a.z);
                float dhl = __logf(dh / a.w);
                float d0 = fabsf(r.x / 0.1f - dx  / 0.1f);
                float d1 = fabsf(r.y / 0.1f - dy  / 0.1f);
                float d2 = fabsf(r.z / 0.2f - dwl / 0.2f);
                float d3 = fabsf(r.w / 0.2f - dhl / 0.2f);
                float s0 = (d0 < 1.0f) ? 0.5f * d0 * d0 : d0 - 0.5f;
                float s1 = (d1 < 1.0f) ? 0.5f * d1 * d1 : d1 - 0.5f;
                float s2 = (d2 < 1.0f) ? 0.5f * d2 * d2 : d2 - 0.5f;
                float s3 = (d3 < 1.0f) ? 0.5f * d3 * d3 : d3 - 0.5f;
                sl_local = s0 + s1 + s2 + s3;
            }
            cl_local = s;
        }
    }

    // deterministic block tree reduction
    r_cl[tid] = cl_local;
    r_sl[tid] = sl_local;
    r_ct[tid] = pos_local;
    __syncthreads();
    for (int off = TPB / 2; off > 0; off >>= 1) {
        if (tid < off) {
            r_cl[tid] += r_cl[tid + off];
            r_sl[tid] += r_sl[tid + off];
            r_ct[tid] += r_ct[tid + off];
        }
        __syncthreads();
    }
    if (tid == 0) {
        int p = b * NB + blockIdx.x;
        g_pcl[p] = r_cl[0];
        g_psl[p] = r_sl[0];
        g_pct[p] = (float)r_ct[0];
    }
}

__global__ void finalize_kernel(float* __restrict__ out, int NB, int B)
{
    __shared__ float s_cls[BMAX];
    __shared__ float s_es[BMAX];
    __shared__ float s_ec[BMAX];

    int w    = threadIdx.x >> 5;
    int lane = threadIdx.x & 31;

    if (w < B) {
        float cl = 0.0f, sl = 0.0f, ct = 0.0f;
        for (int i = lane; i < NB; i += 32) {
            cl += g_pcl[w * NB + i];
            sl += g_psl[w * NB + i];
            ct += g_pct[w * NB + i];
        }
        #pragma unroll
        for (int o = 16; o > 0; o >>= 1) {
            cl += __shfl_down_sync(0xFFFFFFFFu, cl, o);
            sl += __shfl_down_sync(0xFFFFFFFFu, sl, o);
            ct += __shfl_down_sync(0xFFFFFFFFu, ct, o);
        }
        if (lane == 0) {
            float denom    = fmaxf(ct, 1.0f);
            float cls_loss = cl / denom;
            float reg_mean = sl / (denom * 4.0f);
            bool  has_pos  = (ct > 0.0f);
            s_cls[w] = cls_loss;
            s_es[w]  = has_pos ? (reg_mean / denom + reg_mean) : 0.0f;
            s_ec[w]  = has_pos ? 2.0f : 1.0f;
        }
    }
    __syncthreads();
    if (threadIdx.x == 0) {
        float acl = 0.0f, aes = 0.0f, aec = 0.0f;
        for (int i = 0; i < B; i++) {
            acl += s_cls[i];
            aes += s_es[i];
            aec += s_ec[i];
        }
        out[0] = acl / (float)B;
        out[1] = aes / aec;
    }
}

extern "C" void kernel_launch(void* const* d_in, const int* in_sizes, int n_in,
                              void* d_out, int out_size)
{
    const float* cls_ = (const float*)d_in[0];
    const float* reg_ = (const float*)d_in[1];
    const float* anc  = (const float*)d_in[2];
    const float* ann  = (const float*)d_in[3];
    float* out = (float*)d_out;

    int N = in_sizes[2] / 4;
    int B = in_sizes[1] / (N * 4);
    int C = in_sizes[0] / (B * N);
    int M = in_sizes[3] / (B * 5);

    int NB = (N + TPB - 1) / TPB;

    dim3 grid(NB, B);
    assign_kernel<<<grid, TPB>>>(cls_, reg_, anc, ann, N, C, M, NB);
    finalize_kernel<<<1, BMAX * 32>>>(out, NB, B);
}